// round 6
// baseline (speedup 1.0000x reference)
#include <cuda_runtime.h>
#include <cuda_bf16.h>
#include <cstdint>

#define NROWS  65536
#define DDIM   256
#define KCODES 1024
#define NTILES 512
#define MARGIN 1.5e-4f

typedef unsigned int u32; typedef unsigned long long u64;

// gA: [NROWS][512] bf16 rows = [zh(256) | zm(256)];  gB: [KCODES][512] = [ch | cm]
__device__ __align__(16) unsigned char gA[(size_t)NROWS * 1024];
__device__ __align__(16) unsigned char gB[(size_t)KCODES * 1024];
__device__ float g_esq[KCODES];
__device__ float g_zsq[NROWS];
__device__ int   g_idx[NROWS];
__device__ int   g_amb[NROWS];
__device__ int   g_amb_n;
__device__ float g_partial[NTILES];

__device__ __forceinline__ u32 smem_u32(const void* p) {
    u32 a; asm("{ .reg .u64 t; cvta.to.shared.u64 t, %1; cvt.u32.u64 %0, t; }" : "=r"(a) : "l"(p));
    return a;
}
__device__ __forceinline__ void cpasync16(u32 dst, const void* src) {
    u64 g = (u64)__cvta_generic_to_global(src);
    asm volatile("cp.async.cg.shared.global [%0], [%1], 16;" :: "r"(dst), "l"(g) : "memory");
}
__device__ __forceinline__ void ldm_x4(u32* r, u32 addr) {
    asm volatile("ldmatrix.sync.aligned.m8n8.x4.shared.b16 {%0,%1,%2,%3}, [%4];"
                 : "=r"(r[0]), "=r"(r[1]), "=r"(r[2]), "=r"(r[3]) : "r"(addr));
}
__device__ __forceinline__ void mma_bf16(float* d, const u32* a, const u32* b) {
    asm volatile("mma.sync.aligned.m16n8k16.row.col.f32.bf16.bf16.f32 "
                 "{%0,%1,%2,%3}, {%4,%5,%6,%7}, {%8,%9}, {%0,%1,%2,%3};"
                 : "+f"(d[0]), "+f"(d[1]), "+f"(d[2]), "+f"(d[3])
                 : "r"(a[0]), "r"(a[1]), "r"(a[2]), "r"(a[3]), "r"(b[0]), "r"(b[1]));
}

// smem layout (bytes): A 128x520 halves, 2 B stages 128x40 halves, reduce arrays
#define SM_A      0
#define SM_B(s)   (133120 + (s) * 10240)
#define SM_RED    153600
#define SMEM_MMA  156672

__global__ void zero_kernel() { g_amb_n = 0; }

__global__ void esq_kernel(const float* __restrict__ cb) {
    int k = blockIdx.x * blockDim.x + threadIdx.x;
    if (k >= KCODES) return;
    const float* row = cb + (size_t)k * DDIM;
    float s = 0.f;
    for (int d = 0; d < DDIM; d += 4) {
        float4 v = *(const float4*)&row[d];
        s = __fadd_rn(s, __fmul_rn(v.x, v.x)); s = __fadd_rn(s, __fmul_rn(v.y, v.y));
        s = __fadd_rn(s, __fmul_rn(v.z, v.z)); s = __fadd_rn(s, __fmul_rn(v.w, v.w));
    }
    g_esq[k] = s;
}

__global__ void zsq_kernel(const float* __restrict__ z) {
    int n = blockIdx.x * blockDim.x + threadIdx.x;
    if (n >= NROWS) return;
    const float* row = z + (size_t)n * DDIM;
    float s = 0.f;
    for (int d = 0; d < DDIM; d += 4) {
        float4 v = __ldg((const float4*)&row[d]);
        s = __fadd_rn(s, __fmul_rn(v.x, v.x)); s = __fadd_rn(s, __fmul_rn(v.y, v.y));
        s = __fadd_rn(s, __fmul_rn(v.z, v.z)); s = __fadd_rn(s, __fmul_rn(v.w, v.w));
    }
    g_zsq[n] = s;
}

__device__ __forceinline__ void split8(const float* p, uint4& uh, uint4& um) {
    float4 v0 = *(const float4*)p, v1 = *(const float4*)(p + 4);
    float f[8] = {v0.x,v0.y,v0.z,v0.w,v1.x,v1.y,v1.z,v1.w};
    unsigned short h[8], m[8];
    #pragma unroll
    for (int i = 0; i < 8; i++) {
        __nv_bfloat16 hb = __float2bfloat16_rn(f[i]);
        __nv_bfloat16 mb = __float2bfloat16_rn(f[i] - __bfloat162float(hb));
        h[i] = __bfloat16_as_ushort(hb); m[i] = __bfloat16_as_ushort(mb);
    }
    uh = make_uint4((u32)h[0]|((u32)h[1]<<16),(u32)h[2]|((u32)h[3]<<16),(u32)h[4]|((u32)h[5]<<16),(u32)h[6]|((u32)h[7]<<16));
    um = make_uint4((u32)m[0]|((u32)m[1]<<16),(u32)m[2]|((u32)m[3]<<16),(u32)m[4]|((u32)m[5]<<16),(u32)m[6]|((u32)m[7]<<16));
}

__global__ void split_z_kernel(const float* __restrict__ z) {
    int g = blockIdx.x * blockDim.x + threadIdx.x;   // NROWS*32 threads
    int row = g >> 5, d0 = (g & 31) * 8;
    uint4 uh, um; split8(z + (size_t)row * DDIM + d0, uh, um);
    *(uint4*)(gA + ((size_t)row * 512 + d0) * 2)       = uh;
    *(uint4*)(gA + ((size_t)row * 512 + 256 + d0) * 2) = um;
}

__global__ void split_cb_kernel(const float* __restrict__ cb) {
    int g = blockIdx.x * blockDim.x + threadIdx.x;   // KCODES*32 threads
    int code = g >> 5, d0 = (g & 31) * 8;
    uint4 uh, um; split8(cb + (size_t)code * DDIM + d0, uh, um);
    *(uint4*)(gB + ((size_t)code * 512 + d0) * 2)       = uh;
    *(uint4*)(gB + ((size_t)code * 512 + 256 + d0) * 2) = um;
}

__global__ __launch_bounds__(256, 1) void vq_mma_kernel() {
    extern __shared__ unsigned char sm[];
    u32 sb = smem_u32(sm);
    const int t = threadIdx.x, lane = t & 31, w = t >> 5;
    const int mw = w & 3, nw = w >> 2;             // 4 m-warps x 2 n-warps
    const int tile = blockIdx.x;

    // A: 128 rows x 512 halves -> smem (stride 520 halves), one shot
    {
        const unsigned char* src = gA + (size_t)tile * 131072;
        #pragma unroll 4
        for (int i = t; i < 8192; i += 256) {
            int r = i >> 6, c = i & 63;
            cpasync16(sb + SM_A + r * 1040 + c * 16, src + (size_t)r * 1024 + c * 16);
        }
        asm volatile("cp.async.commit_group;" ::: "memory");
    }

    float m1[4], m2[4]; int i1[4];
    #pragma unroll
    for (int s = 0; s < 4; s++) { m1[s] = 3.4e38f; m2[s] = 3.4e38f; i1[s] = 0; }

    for (int nc = 0; nc < 8; nc++) {
        // load B chunk q into stage s: pass p=q>>3, kc=(q&7)*32
        #define LOADB(q, s) do { \
            int _p = (q) >> 3, _kc = ((q) & 7) * 32; \
            int _bc = (_p == 1 ? 256 : 0) + _kc; \
            const unsigned char* _src = gB + ((size_t)(nc * 128) * 512 + _bc) * 2; \
            for (int _i = t; _i < 512; _i += 256) { \
                int _r = _i >> 2, _c = _i & 3; \
                cpasync16(sb + SM_B(s) + _r * 80 + _c * 16, _src + (size_t)_r * 1024 + _c * 16); \
            } \
            asm volatile("cp.async.commit_group;" ::: "memory"); \
        } while (0)

        LOADB(0, 0);
        float acc[2][8][4];
        #pragma unroll
        for (int a = 0; a < 2; a++)
            #pragma unroll
            for (int b = 0; b < 8; b++)
                #pragma unroll
                for (int c = 0; c < 4; c++) acc[a][b][c] = 0.f;

        for (int q = 0; q < 24; q++) {
            if (q < 23) { LOADB(q + 1, (q + 1) & 1); }
            if (q < 23) asm volatile("cp.async.wait_group 1;" ::: "memory");
            else        asm volatile("cp.async.wait_group 0;" ::: "memory");
            __syncthreads();
            int p = q >> 3, kc = (q & 7) * 32;
            int acol = (p == 2 ? 256 : 0) + kc;
            u32 bstage = sb + SM_B(q & 1);
            #pragma unroll
            for (int ks = 0; ks < 2; ks++) {
                u32 afr[2][4];
                #pragma unroll
                for (int mt = 0; mt < 2; mt++) {
                    int row = mw * 32 + mt * 16 + (lane & 15);
                    int col = acol + ks * 16 + (lane >> 4) * 8;
                    ldm_x4(afr[mt], sb + SM_A + row * 1040 + col * 2);
                }
                u32 bfr[8][2];
                #pragma unroll
                for (int np = 0; np < 4; np++) {
                    int nrow = np * 16 + (lane & 7) + ((lane >> 4) & 1) * 8 + nw * 64;
                    int col  = ks * 16 + ((lane >> 3) & 1) * 8;
                    u32 r4[4]; ldm_x4(r4, bstage + nrow * 80 + col * 2);
                    bfr[np*2][0] = r4[0]; bfr[np*2][1] = r4[1];
                    bfr[np*2+1][0] = r4[2]; bfr[np*2+1][1] = r4[3];
                }
                #pragma unroll
                for (int mt = 0; mt < 2; mt++)
                    #pragma unroll
                    for (int nt = 0; nt < 8; nt++)
                        mma_bf16(acc[mt][nt], afr[mt], bfr[nt]);
            }
            __syncthreads();
        }
        // epilogue: running top-2 per lane-row-slot; codes for this nc chunk
        float e[16];
        #pragma unroll
        for (int nt = 0; nt < 8; nt++)
            #pragma unroll
            for (int j = 0; j < 2; j++)
                e[nt*2+j] = __ldg(&g_esq[nc*128 + nw*64 + nt*8 + 2*(lane & 3) + j]);
        #pragma unroll
        for (int mt = 0; mt < 2; mt++)
            #pragma unroll
            for (int h = 0; h < 2; h++) {
                int slot = mt * 2 + h;
                #pragma unroll
                for (int nt = 0; nt < 8; nt++)
                    #pragma unroll
                    for (int j = 0; j < 2; j++) {
                        float d = fmaf(-2.f, acc[mt][nt][h*2+j], e[nt*2+j]);
                        int code = nc*128 + nw*64 + nt*8 + 2*(lane & 3) + j;
                        if (d < m1[slot]) { m2[slot] = m1[slot]; m1[slot] = d; i1[slot] = code; }
                        else if (d < m2[slot]) m2[slot] = d;
                    }
            }
    }

    // merge 4 lanes of each quad (share same rows)
    #pragma unroll
    for (int slot = 0; slot < 4; slot++) {
        #pragma unroll
        for (int msk = 1; msk <= 2; msk <<= 1) {
            float om1 = __shfl_xor_sync(0xffffffffu, m1[slot], msk);
            float om2 = __shfl_xor_sync(0xffffffffu, m2[slot], msk);
            int   oi  = __shfl_xor_sync(0xffffffffu, i1[slot], msk);
            if (om1 < m1[slot] || (om1 == m1[slot] && oi < i1[slot])) {
                m2[slot] = fminf(m1[slot], fminf(m2[slot], om2));
                m1[slot] = om1; i1[slot] = oi;
            } else {
                m2[slot] = fminf(om1, fminf(m2[slot], om2));
            }
        }
    }
    float* rm1 = (float*)(sm + SM_RED);
    float* rm2 = rm1 + 256;
    int*   ri  = (int*)(rm2 + 256);
    if ((lane & 3) == 0) {
        #pragma unroll
        for (int slot = 0; slot < 4; slot++) {
            int row = mw * 32 + (slot & 1) * 8 + (slot >> 1) * 16 + (lane >> 2);
            rm1[nw * 128 + row] = m1[slot];
            rm2[nw * 128 + row] = m2[slot];
            ri [nw * 128 + row] = i1[slot];
        }
    }
    __syncthreads();
    if (t < 128) {
        float a1 = rm1[t], a2 = rm2[t]; int ai = ri[t];
        float b1 = rm1[128 + t], b2 = rm2[128 + t]; int bi = ri[128 + t];
        float f1, f2; int fi;
        if (b1 < a1 || (b1 == a1 && bi < ai)) { f1 = b1; fi = bi; f2 = fminf(a1, fminf(a2, b2)); }
        else                                   { f1 = a1; fi = ai; f2 = fminf(b1, fminf(a2, b2)); }
        int row = tile * 128 + t;
        g_idx[row] = fi;
        if (f2 - f1 <= MARGIN) { int p = atomicAdd(&g_amb_n, 1); g_amb[p] = row; }
    }
}

// exact re-resolution (bit-identical to R2-validated path) for ambiguous rows
__global__ void fixup_kernel(const float* __restrict__ z, const float* __restrict__ cb) {
    int n = g_amb_n;
    int w = (blockIdx.x * blockDim.x + threadIdx.x) >> 5, lane = threadIdx.x & 31;
    int nw = (gridDim.x * blockDim.x) >> 5;
    for (int a = w; a < n; a += nw) {
        int row = g_amb[a];
        const float* zr = z + (size_t)row * DDIM;
        float zsq = g_zsq[row];
        float bv = 3.4e38f; int bi = 0;
        for (int k = lane; k < KCODES; k += 32) {
            const float* er = cb + (size_t)k * DDIM;
            float c = 0.f;
            for (int d = 0; d < DDIM; d += 4) {
                float4 zv = __ldg((const float4*)(zr + d));
                float4 ev = __ldg((const float4*)(er + d));
                c = fmaf(zv.x, ev.x, c); c = fmaf(zv.y, ev.y, c);
                c = fmaf(zv.z, ev.z, c); c = fmaf(zv.w, ev.w, c);
            }
            float dist = __fadd_rn(__fsub_rn(zsq, __fmul_rn(2.f, c)), g_esq[k]);
            if (dist < bv) { bv = dist; bi = k; }
        }
        for (int off = 16; off; off >>= 1) {
            float ov = __shfl_down_sync(0xffffffffu, bv, off);
            int   oi = __shfl_down_sync(0xffffffffu, bi, off);
            if (ov < bv || (ov == bv && oi < bi)) { bv = ov; bi = oi; }
        }
        if (lane == 0) g_idx[row] = bi;
    }
}

__global__ __launch_bounds__(256) void gather_kernel(const float* __restrict__ z,
                                                     const float* __restrict__ cb,
                                                     float* __restrict__ out) {
    __shared__ int sidx[128]; __shared__ float red[256];
    int t = threadIdx.x, rowbase = blockIdx.x * 128;
    if (t < 128) sidx[t] = g_idx[rowbase + t];
    __syncthreads();
    float lsum = 0.f;
    for (int r = 0; r < 128; r++) {
        int idx = sidx[r];
        float zq = cb[(size_t)idx * DDIM + t];
        float ze = z[(size_t)(rowbase + r) * DDIM + t];
        out[(size_t)(rowbase + r) * DDIM + t] = zq;
        float df = zq - ze; lsum = fmaf(df, df, lsum);
    }
    red[t] = lsum; __syncthreads();
    for (int s = 128; s; s >>= 1) { if (t < s) red[t] += red[t + s]; __syncthreads(); }
    if (t == 0) g_partial[blockIdx.x] = red[0];
}

__global__ void finalize_kernel(float* __restrict__ out, int out_size) {
    __shared__ float red[512];
    int t = threadIdx.x;
    red[t] = g_partial[t];
    __syncthreads();
    for (int s = 256; s; s >>= 1) { if (t < s) red[t] += red[t + s]; __syncthreads(); }
    float loss = red[0] / (float)((long long)NROWS * DDIM);
    const long long base = (long long)NROWS * DDIM;
    for (long long i = base + t; i < (long long)out_size; i += blockDim.x) out[i] = loss;
}

extern "C" void kernel_launch(void* const* d_in, const int* in_sizes, int n_in,
                              void* d_out, int out_size) {
    const float* z  = (const float*)d_in[0];
    const float* cb = (const float*)d_in[1];
    if (n_in >= 2 && in_sizes[0] == KCODES * DDIM && in_sizes[1] == NROWS * DDIM) {
        z = (const float*)d_in[1]; cb = (const float*)d_in[0];
    }
    float* out = (float*)d_out;
    cudaFuncSetAttribute(vq_mma_kernel, cudaFuncAttributeMaxDynamicSharedMemorySize, SMEM_MMA);

    zero_kernel<<<1, 1>>>();
    esq_kernel<<<4, 256>>>(cb);
    zsq_kernel<<<NROWS / 256, 256>>>(z);
    split_z_kernel<<<8192, 256>>>(z);
    split_cb_kernel<<<128, 256>>>(cb);
    vq_mma_kernel<<<NTILES, 256, SMEM_MMA>>>();
    fixup_kernel<<<512, 128>>>(z, cb);
    gather_kernel<<<512, 256>>>(z, cb, out);
    finalize_kernel<<<1, 512>>>(out, out_size);
}

// round 7
// speedup vs baseline: 1.3341x; 1.3341x over previous
#include <cuda_runtime.h>
#include <cuda_bf16.h>
#include <cstdint>

#define NROWS  65536
#define DDIM   256
#define KCODES 1024
#define NTILES 512
#define MARGIN 1e-3f

typedef unsigned int u32; typedef unsigned long long u64;

// gA: [NROWS][256] bf16 (zh);  gB: [KCODES][256] bf16 (ch)
__device__ __align__(16) unsigned char gA[(size_t)NROWS * 512];
__device__ __align__(16) unsigned char gB[(size_t)KCODES * 512];
__device__ float g_esq[KCODES];
__device__ float g_zsq[NROWS];
__device__ int   g_idx[NROWS];
__device__ int   g_amb[NROWS];
__device__ int2  g_ambc[NROWS];
__device__ int   g_full[NROWS];
__device__ int   g_amb_n;
__device__ int   g_full_n;
__device__ float g_partial[NTILES];

__device__ __forceinline__ u32 smem_u32(const void* p) {
    u32 a; asm("{ .reg .u64 t; cvta.to.shared.u64 t, %1; cvt.u32.u64 %0, t; }" : "=r"(a) : "l"(p));
    return a;
}
__device__ __forceinline__ void cpasync16(u32 dst, const void* src) {
    u64 g = (u64)__cvta_generic_to_global(src);
    asm volatile("cp.async.cg.shared.global [%0], [%1], 16;" :: "r"(dst), "l"(g) : "memory");
}
__device__ __forceinline__ void ldm_x4(u32* r, u32 addr) {
    asm volatile("ldmatrix.sync.aligned.m8n8.x4.shared.b16 {%0,%1,%2,%3}, [%4];"
                 : "=r"(r[0]), "=r"(r[1]), "=r"(r[2]), "=r"(r[3]) : "r"(addr));
}
__device__ __forceinline__ void mma_bf16(float* d, const u32* a, const u32* b) {
    asm volatile("mma.sync.aligned.m16n8k16.row.col.f32.bf16.bf16.f32 "
                 "{%0,%1,%2,%3}, {%4,%5,%6,%7}, {%8,%9}, {%0,%1,%2,%3};"
                 : "+f"(d[0]), "+f"(d[1]), "+f"(d[2]), "+f"(d[3])
                 : "r"(a[0]), "r"(a[1]), "r"(a[2]), "r"(a[3]), "r"(b[0]), "r"(b[1]));
}
// lexicographic top-3 insert (strict, lowest-index on ties)
__device__ __forceinline__ void lexins(float (&v)[3], int (&ix)[3], float d, int c) {
    if (d < v[2] || (d == v[2] && c < ix[2])) {
        if (d < v[1] || (d == v[1] && c < ix[1])) {
            v[2] = v[1]; ix[2] = ix[1];
            if (d < v[0] || (d == v[0] && c < ix[0])) {
                v[1] = v[0]; ix[1] = ix[0]; v[0] = d; ix[0] = c;
            } else { v[1] = d; ix[1] = c; }
        } else { v[2] = d; ix[2] = c; }
    }
}

// smem: A 128x264 halves (528B rows), 2 B stages 128x40 halves, reduce arrays
#define SM_A      0
#define SM_B      67584
#define SM_RED    88064          // 768 floats + 768 ints
#define SMEM_MMA  94208

__global__ void zero_kernel() { g_amb_n = 0; g_full_n = 0; }

__global__ void esq_kernel(const float* __restrict__ cb) {
    int k = blockIdx.x * blockDim.x + threadIdx.x;
    if (k >= KCODES) return;
    const float* row = cb + (size_t)k * DDIM;
    float s = 0.f;
    for (int d = 0; d < DDIM; d += 4) {
        float4 v = *(const float4*)&row[d];
        s = __fadd_rn(s, __fmul_rn(v.x, v.x)); s = __fadd_rn(s, __fmul_rn(v.y, v.y));
        s = __fadd_rn(s, __fmul_rn(v.z, v.z)); s = __fadd_rn(s, __fmul_rn(v.w, v.w));
    }
    g_esq[k] = s;
}

__global__ void zsq_kernel(const float* __restrict__ z) {
    int n = blockIdx.x * blockDim.x + threadIdx.x;
    if (n >= NROWS) return;
    const float* row = z + (size_t)n * DDIM;
    float s = 0.f;
    for (int d = 0; d < DDIM; d += 4) {
        float4 v = __ldg((const float4*)&row[d]);
        s = __fadd_rn(s, __fmul_rn(v.x, v.x)); s = __fadd_rn(s, __fmul_rn(v.y, v.y));
        s = __fadd_rn(s, __fmul_rn(v.z, v.z)); s = __fadd_rn(s, __fmul_rn(v.w, v.w));
    }
    g_zsq[n] = s;
}

__device__ __forceinline__ uint4 cvt8(const float* p) {
    float4 v0 = *(const float4*)p, v1 = *(const float4*)(p + 4);
    float f[8] = {v0.x,v0.y,v0.z,v0.w,v1.x,v1.y,v1.z,v1.w};
    unsigned short h[8];
    #pragma unroll
    for (int i = 0; i < 8; i++) h[i] = __bfloat16_as_ushort(__float2bfloat16_rn(f[i]));
    return make_uint4((u32)h[0]|((u32)h[1]<<16),(u32)h[2]|((u32)h[3]<<16),
                      (u32)h[4]|((u32)h[5]<<16),(u32)h[6]|((u32)h[7]<<16));
}

__global__ void split_z_kernel(const float* __restrict__ z) {
    int g = blockIdx.x * blockDim.x + threadIdx.x;   // NROWS*32
    int row = g >> 5, d0 = (g & 31) * 8;
    *(uint4*)(gA + ((size_t)row * 256 + d0) * 2) = cvt8(z + (size_t)row * DDIM + d0);
}
__global__ void split_cb_kernel(const float* __restrict__ cb) {
    int g = blockIdx.x * blockDim.x + threadIdx.x;   // KCODES*32
    int code = g >> 5, d0 = (g & 31) * 8;
    *(uint4*)(gB + ((size_t)code * 256 + d0) * 2) = cvt8(cb + (size_t)code * DDIM + d0);
}

__global__ __launch_bounds__(256, 1) void vq_mma_kernel() {
    extern __shared__ unsigned char sm[];
    u32 sb = smem_u32(sm);
    const int t = threadIdx.x, lane = t & 31, w = t >> 5;
    const int mw = w & 3, nw = w >> 2;             // 4 m-warps x 2 n-warps
    const int tile = blockIdx.x;

    {   // A: 128 rows x 256 halves -> smem stride 528B
        const unsigned char* src = gA + (size_t)tile * 65536;
        #pragma unroll
        for (int i = t; i < 4096; i += 256) {
            int r = i >> 5, c = i & 31;
            cpasync16(sb + SM_A + r * 528 + c * 16, src + (size_t)r * 512 + c * 16);
        }
        asm volatile("cp.async.commit_group;" ::: "memory");
    }

    float t3v[4][3]; int t3i[4][3];
    #pragma unroll
    for (int s = 0; s < 4; s++)
        #pragma unroll
        for (int j = 0; j < 3; j++) { t3v[s][j] = 3.4e38f; t3i[s][j] = 0x7fffffff; }

    #define LOADB(gq) do { \
        int _nc = (gq) >> 3, _q = (gq) & 7; \
        const unsigned char* _src = gB + (size_t)(_nc * 128) * 512 + _q * 64; \
        u32 _dst = sb + SM_B + ((gq) & 1) * 10240; \
        _Pragma("unroll") \
        for (int _i = t; _i < 512; _i += 256) { \
            int _r = _i >> 2, _c = _i & 3; \
            cpasync16(_dst + _r * 80 + _c * 16, _src + (size_t)_r * 512 + _c * 16); \
        } \
        asm volatile("cp.async.commit_group;" ::: "memory"); \
    } while (0)

    LOADB(0);
    for (int nc = 0; nc < 8; nc++) {
        float acc[2][8][4];
        #pragma unroll
        for (int a = 0; a < 2; a++)
            #pragma unroll
            for (int b = 0; b < 8; b++)
                #pragma unroll
                for (int c = 0; c < 4; c++) acc[a][b][c] = 0.f;

        for (int q = 0; q < 8; q++) {
            int gq = nc * 8 + q;
            if (gq < 63) { LOADB(gq + 1); asm volatile("cp.async.wait_group 1;" ::: "memory"); }
            else         { asm volatile("cp.async.wait_group 0;" ::: "memory"); }
            __syncthreads();
            int acol = q * 32;
            u32 bstage = sb + SM_B + (gq & 1) * 10240;
            #pragma unroll
            for (int ks = 0; ks < 2; ks++) {
                u32 afr[2][4];
                #pragma unroll
                for (int mt = 0; mt < 2; mt++) {
                    int row = mw * 32 + mt * 16 + (lane & 15);
                    int col = acol + ks * 16 + (lane >> 4) * 8;
                    ldm_x4(afr[mt], sb + SM_A + row * 528 + col * 2);
                }
                u32 bfr[8][2];
                #pragma unroll
                for (int np = 0; np < 4; np++) {
                    int nrow = nw * 64 + np * 16 + (lane & 7) + ((lane >> 4) & 1) * 8;
                    int col  = ks * 16 + ((lane >> 3) & 1) * 8;
                    u32 r4[4]; ldm_x4(r4, bstage + nrow * 80 + col * 2);
                    bfr[np*2][0] = r4[0]; bfr[np*2][1] = r4[1];
                    bfr[np*2+1][0] = r4[2]; bfr[np*2+1][1] = r4[3];
                }
                #pragma unroll
                for (int mt = 0; mt < 2; mt++)
                    #pragma unroll
                    for (int nt = 0; nt < 8; nt++)
                        mma_bf16(acc[mt][nt], afr[mt], bfr[nt]);
            }
            __syncthreads();
        }
        float e[16];
        #pragma unroll
        for (int nt = 0; nt < 8; nt++)
            #pragma unroll
            for (int j = 0; j < 2; j++)
                e[nt*2+j] = __ldg(&g_esq[nc*128 + nw*64 + nt*8 + 2*(lane & 3) + j]);
        #pragma unroll
        for (int mt = 0; mt < 2; mt++)
            #pragma unroll
            for (int h = 0; h < 2; h++) {
                #pragma unroll
                for (int nt = 0; nt < 8; nt++)
                    #pragma unroll
                    for (int j = 0; j < 2; j++) {
                        float d = fmaf(-2.f, acc[mt][nt][h*2+j], e[nt*2+j]);
                        int code = nc*128 + nw*64 + nt*8 + 2*(lane & 3) + j;
                        lexins(t3v[mt*2+h], t3i[mt*2+h], d, code);
                    }
            }
    }

    // merge quad lanes (codes split across lane&3)
    #pragma unroll
    for (int s = 0; s < 4; s++) {
        #pragma unroll
        for (int msk = 1; msk <= 2; msk <<= 1) {
            float ov[3]; int oi[3];
            #pragma unroll
            for (int j = 0; j < 3; j++) {
                ov[j] = __shfl_xor_sync(0xffffffffu, t3v[s][j], msk);
                oi[j] = __shfl_xor_sync(0xffffffffu, t3i[s][j], msk);
            }
            #pragma unroll
            for (int j = 0; j < 3; j++) lexins(t3v[s], t3i[s], ov[j], oi[j]);
        }
    }
    float* rv = (float*)(sm + SM_RED);
    int*   ri = (int*)(sm + SM_RED + 3072);
    if ((lane & 3) == 0) {
        #pragma unroll
        for (int s = 0; s < 4; s++) {
            int row = mw * 32 + (s >> 1) * 16 + (s & 1) * 8 + (lane >> 2);
            int base = (nw * 128 + row) * 3;
            #pragma unroll
            for (int j = 0; j < 3; j++) { rv[base+j] = t3v[s][j]; ri[base+j] = t3i[s][j]; }
        }
    }
    __syncthreads();
    if (t < 128) {
        float v[3]; int ix[3];
        #pragma unroll
        for (int j = 0; j < 3; j++) { v[j] = rv[t*3+j]; ix[j] = ri[t*3+j]; }
        #pragma unroll
        for (int j = 0; j < 3; j++) lexins(v, ix, rv[(128+t)*3+j], ri[(128+t)*3+j]);
        int row = tile * 128 + t;
        g_idx[row] = ix[0];
        if (v[1] - v[0] <= MARGIN) {
            if (v[2] - v[0] > MARGIN) {
                int p = atomicAdd(&g_amb_n, 1); g_amb[p] = row; g_ambc[p] = make_int2(ix[0], ix[1]);
            } else {
                int p = atomicAdd(&g_full_n, 1); g_full[p] = row;
            }
        }
    }
}

// exact 2-candidate duel, bit-exact R2 numerics
__global__ void duel_kernel(const float* __restrict__ z, const float* __restrict__ cb) {
    int n = g_amb_n;
    for (int a = blockIdx.x * blockDim.x + threadIdx.x; a < n; a += gridDim.x * blockDim.x) {
        int row = g_amb[a]; int2 cc = g_ambc[a];
        const float* zr = z + (size_t)row * DDIM;
        const float* ea = cb + (size_t)cc.x * DDIM;
        const float* eb = cb + (size_t)cc.y * DDIM;
        float ca = 0.f, cv = 0.f;
        for (int d = 0; d < DDIM; d += 4) {
            float4 zv = __ldg((const float4*)(zr + d));
            float4 av = __ldg((const float4*)(ea + d));
            float4 bv = __ldg((const float4*)(eb + d));
            ca = fmaf(zv.x, av.x, ca); cv = fmaf(zv.x, bv.x, cv);
            ca = fmaf(zv.y, av.y, ca); cv = fmaf(zv.y, bv.y, cv);
            ca = fmaf(zv.z, av.z, ca); cv = fmaf(zv.z, bv.z, cv);
            ca = fmaf(zv.w, av.w, ca); cv = fmaf(zv.w, bv.w, cv);
        }
        float zq = g_zsq[row];
        float da = __fadd_rn(__fsub_rn(zq, __fmul_rn(2.f, ca)), g_esq[cc.x]);
        float db = __fadd_rn(__fsub_rn(zq, __fmul_rn(2.f, cv)), g_esq[cc.y]);
        g_idx[row] = (db < da || (db == da && cc.y < cc.x)) ? cc.y : cc.x;
    }
}

// exact full row scan (broadcast codebook, z transposed in smem), 8 rows/tile
__global__ __launch_bounds__(256) void fullscan_kernel(const float* __restrict__ z,
                                                       const float* __restrict__ cb) {
    __shared__ float zs[256 * 9];
    __shared__ float s_zsq[8];
    __shared__ float s_bv[64]; __shared__ int s_bi[64];
    int n = g_full_n;
    int t = threadIdx.x, lane = t & 31, w = t >> 5;
    for (int tile = blockIdx.x; tile * 8 < n; tile += gridDim.x) {
        int cnt = min(8, n - tile * 8);
        __syncthreads();
        for (int r = 0; r < 8; r++) {
            if (r < cnt) {
                int row = g_full[tile * 8 + r];
                zs[t * 9 + r] = z[(size_t)row * DDIM + t];
                if (t == 0) s_zsq[r] = g_zsq[row];
            } else { zs[t * 9 + r] = 0.f; if (t == 0) s_zsq[r] = 0.f; }
        }
        __syncthreads();
        int r = lane & 7, ks = lane >> 3;
        float bv = 3.4e38f; int bi = 0x7fffffff;
        float zq = s_zsq[r];
        for (int j = 0; j < 32; j++) {
            int k = j * 32 + w * 4 + ks;
            const float* er = cb + (size_t)k * DDIM;
            float c = 0.f;
            for (int d = 0; d < DDIM; d += 4) {
                float4 ev = __ldg((const float4*)(er + d));
                c = fmaf(zs[(d+0)*9 + r], ev.x, c);
                c = fmaf(zs[(d+1)*9 + r], ev.y, c);
                c = fmaf(zs[(d+2)*9 + r], ev.z, c);
                c = fmaf(zs[(d+3)*9 + r], ev.w, c);
            }
            float dist = __fadd_rn(__fsub_rn(zq, __fmul_rn(2.f, c)), __ldg(&g_esq[k]));
            if (dist < bv || (dist == bv && k < bi)) { bv = dist; bi = k; }
        }
        #pragma unroll
        for (int msk = 8; msk <= 16; msk <<= 1) {
            float ov = __shfl_xor_sync(0xffffffffu, bv, msk);
            int   oi = __shfl_xor_sync(0xffffffffu, bi, msk);
            if (ov < bv || (ov == bv && oi < bi)) { bv = ov; bi = oi; }
        }
        if (ks == 0) { s_bv[w * 8 + r] = bv; s_bi[w * 8 + r] = bi; }
        __syncthreads();
        if (t < cnt) {
            float fv = s_bv[t]; int fi = s_bi[t];
            #pragma unroll
            for (int ww = 1; ww < 8; ww++) {
                float ov = s_bv[ww * 8 + t]; int oi = s_bi[ww * 8 + t];
                if (ov < fv || (ov == fv && oi < fi)) { fv = ov; fi = oi; }
            }
            g_idx[g_full[tile * 8 + t]] = fi;
        }
    }
}

__global__ __launch_bounds__(256) void gather_kernel(const float* __restrict__ z,
                                                     const float* __restrict__ cb,
                                                     float* __restrict__ out) {
    __shared__ int sidx[128]; __shared__ float red[256];
    int t = threadIdx.x, rowbase = blockIdx.x * 128;
    if (t < 128) sidx[t] = g_idx[rowbase + t];
    __syncthreads();
    float lsum = 0.f;
    for (int r = 0; r < 128; r++) {
        int idx = sidx[r];
        float zq = cb[(size_t)idx * DDIM + t];
        float ze = z[(size_t)(rowbase + r) * DDIM + t];
        out[(size_t)(rowbase + r) * DDIM + t] = zq;
        float df = zq - ze; lsum = fmaf(df, df, lsum);
    }
    red[t] = lsum; __syncthreads();
    for (int s = 128; s; s >>= 1) { if (t < s) red[t] += red[t + s]; __syncthreads(); }
    if (t == 0) g_partial[blockIdx.x] = red[0];
}

__global__ void finalize_kernel(float* __restrict__ out, int out_size) {
    __shared__ float red[512];
    int t = threadIdx.x;
    red[t] = g_partial[t];
    __syncthreads();
    for (int s = 256; s; s >>= 1) { if (t < s) red[t] += red[t + s]; __syncthreads(); }
    float loss = red[0] / (float)((long long)NROWS * DDIM);
    const long long base = (long long)NROWS * DDIM;
    for (long long i = base + t; i < (long long)out_size; i += blockDim.x) out[i] = loss;
}

extern "C" void kernel_launch(void* const* d_in, const int* in_sizes, int n_in,
                              void* d_out, int out_size) {
    const float* z  = (const float*)d_in[0];
    const float* cb = (const float*)d_in[1];
    if (n_in >= 2 && in_sizes[0] == KCODES * DDIM && in_sizes[1] == NROWS * DDIM) {
        z = (const float*)d_in[1]; cb = (const float*)d_in[0];
    }
    float* out = (float*)d_out;
    cudaFuncSetAttribute(vq_mma_kernel, cudaFuncAttributeMaxDynamicSharedMemorySize, SMEM_MMA);

    zero_kernel<<<1, 1>>>();
    esq_kernel<<<4, 256>>>(cb);
    zsq_kernel<<<NROWS / 256, 256>>>(z);
    split_z_kernel<<<8192, 256>>>(z);
    split_cb_kernel<<<128, 256>>>(cb);
    vq_mma_kernel<<<NTILES, 256, SMEM_MMA>>>();
    duel_kernel<<<256, 256>>>(z, cb);
    fullscan_kernel<<<148, 256>>>(z, cb);
    gather_kernel<<<512, 256>>>(z, cb, out);
    finalize_kernel<<<1, 512>>>(out, out_size);
}